// round 14
// baseline (speedup 1.0000x reference)
#include <cuda_runtime.h>
#include <cuda_fp16.h>
#include <cstdint>
#include <cfloat>

// Problem constants
#define N_ROWS  131072
#define DIMS    64
#define KENT    4096
#define GM      128            // rows per CTA
#define GNB     256            // codes per pipeline super-chunk
#define NSUB    4              // 64-code sub-blocks per super-chunk
#define GN      64             // codes per sub-block (= cmax granularity)
#define NBIG    (KENT / GNB)   // 16
#define NCHUNK  (KENT / GN)    // 64 (cmax chunks)
#define GBLOCKS (N_ROWS / GM)  // 1024
#define ETHREADS 256
#define EBLOCKS (N_ROWS / ETHREADS)
#define TAU1    0.03f          // fp16 dist margin -> flagged for exact candidate rescore
#define GTH     0.04f          // g-scale chunk-candidate slack (~25 sigma)

// gemm1 smem
#define SROW1   144
#define A_BYTES (GM * SROW1)                  // 18432
#define B1_OFF  A_BYTES
#define B1_BYTES (GNB * SROW1)                // 36864 per buffer
#define EN1_OFF (B1_OFF + 2 * B1_BYTES)       // 92160
#define SMEM1_TOTAL (EN1_OFF + 2 * 1024)      // 94208

// Scratch
__device__ __half g_bh[(size_t)KENT * DIMS];           // fp16 codebook, 512 KB
__device__ float  g_cmax[(size_t)NCHUNK * N_ROWS];     // CHUNK-MAJOR [chunk][row], 33.5 MB
__device__ float  g_enorm[KENT];
__device__ float  g_en2[KENT];
__device__ float  g_bsum[EBLOCKS];
__device__ int    g_idx[N_ROWS];
__device__ int    g_list[N_ROWS];
__device__ int    g_cnt;

// ---------------- helpers ----------------
__device__ __forceinline__ uint32_t smem_u32(const void* p) {
    uint32_t a;
    asm("{ .reg .u64 t; cvta.to.shared.u64 t, %1; cvt.u32.u64 %0, t; }" : "=r"(a) : "l"(p));
    return a;
}
#define CP_ASYNC16(dst, src) \
    asm volatile("cp.async.cg.shared.global [%0], [%1], 16;" :: "r"(dst), "l"(src))
#define CP_COMMIT() asm volatile("cp.async.commit_group;" ::: "memory")
#define CP_WAIT(n)  asm volatile("cp.async.wait_group %0;" :: "n"(n) : "memory")

#define LDSM4(r0, r1, r2, r3, a) \
    asm volatile("ldmatrix.sync.aligned.m8n8.x4.shared.b16 {%0,%1,%2,%3}, [%4];" \
        : "=r"(r0), "=r"(r1), "=r"(r2), "=r"(r3) : "r"(a))

#define MMA16816(d, a, b0_, b1_) \
    asm volatile("mma.sync.aligned.m16n8k16.row.col.f32.f16.f16.f32 " \
        "{%0,%1,%2,%3}, {%4,%5,%6,%7}, {%8,%9}, {%0,%1,%2,%3};" \
        : "+f"((d)[0]), "+f"((d)[1]), "+f"((d)[2]), "+f"((d)[3]) \
        : "r"((a)[0]), "r"((a)[1]), "r"((a)[2]), "r"((a)[3]), "r"(b0_), "r"(b1_))

__device__ __forceinline__ void upd(float& b, float& b2, int& id, float g, int c) {
    if (g > b) { b2 = b; b = g; id = c; }
    else if (g > b2) { b2 = g; }
}

// ---------- kernel 0: norms (fp64->fp32), -en/2, counter reset ----------
__global__ void vq_init(const float* __restrict__ cb) {
    int k = blockIdx.x * blockDim.x + threadIdx.x;
    if (k == 0) g_cnt = 0;
    if (k < KENT) {
        const float4* p = (const float4*)(cb + (size_t)k * DIMS);
        double s = 0.0;
        #pragma unroll
        for (int i = 0; i < DIMS / 4; i++) {
            float4 v = p[i];
            s += (double)v.x * v.x + (double)v.y * v.y
               + (double)v.z * v.z + (double)v.w * v.w;
        }
        g_enorm[k] = (float)s;
        g_en2[k]   = (float)(-0.5 * s);
    }
}

// ---------- prep: cb -> fp16 ----------
__global__ void vq_prep_cb(const float* __restrict__ cb) {
    int i = blockIdx.x * blockDim.x + threadIdx.x;
    if (i < KENT * DIMS / 4) {
        float4 v = ((const float4*)cb)[i];
        __half2* o = (__half2*)(g_bh + (size_t)i * 4);
        o[0] = __floats2half2_rn(v.x, v.y);
        o[1] = __floats2half2_rn(v.z, v.w);
    }
}

// ---------- gemm1 building blocks ----------
struct Top2 {
    float bestA, best2A, bestB, best2B;
    int   idxA, idxB;
};

__device__ __forceinline__ void mma_sub(float (&d)[8][4], uint32_t Bs,
                                        const uint32_t (&af)[4][4],
                                        uint32_t n_part, uint32_t koff_b) {
    #pragma unroll
    for (int t = 0; t < 8; t++)
        #pragma unroll
        for (int qq = 0; qq < 4; qq++) d[t][qq] = 0.0f;
    #pragma unroll
    for (int k = 0; k < 4; k++) {
        #pragma unroll
        for (int jp = 0; jp < 4; jp++) {
            uint32_t b0, b1, b2, b3;
            LDSM4(b0, b1, b2, b3, Bs + (16 * jp + n_part) * SROW1 + k * 32 + koff_b);
            MMA16816(d[2 * jp],     af[k], b0, b1);
            MMA16816(d[2 * jp + 1], af[k], b2, b3);
        }
    }
}

__device__ __forceinline__ void epilogue(const float (&d)[8][4], const float2* env,
                                         int pidx, int chunk, Top2& tp,
                                         int rowA_g, int rowB_g) {
    float mA = -FLT_MAX, mB = -FLT_MAX;
    #pragma unroll
    for (int t = 0; t < 8; t++) {
        float2 e = env[t * 4 + pidx];
        mA = fmaxf(mA, fmaxf(d[t][0] + e.x, d[t][1] + e.y));
        mB = fmaxf(mB, fmaxf(d[t][2] + e.x, d[t][3] + e.y));
    }
    mA = fmaxf(mA, __shfl_xor_sync(0xffffffffu, mA, 1));
    mA = fmaxf(mA, __shfl_xor_sync(0xffffffffu, mA, 2));
    mB = fmaxf(mB, __shfl_xor_sync(0xffffffffu, mB, 1));
    mB = fmaxf(mB, __shfl_xor_sync(0xffffffffu, mB, 2));

    if (pidx == 0) {   // chunk-major -> coalesced across the CTA's rows
        g_cmax[(size_t)chunk * N_ROWS + rowA_g] = mA;
        g_cmax[(size_t)chunk * N_ROWS + rowB_g] = mB;
    }

    const int c_base = chunk * GN + pidx * 2;
    if (mA > tp.best2A) {
        #pragma unroll
        for (int t = 0; t < 8; t++) {
            float2 e = env[t * 4 + pidx];
            upd(tp.bestA, tp.best2A, tp.idxA, d[t][0] + e.x, c_base + t * 8);
            upd(tp.bestA, tp.best2A, tp.idxA, d[t][1] + e.y, c_base + t * 8 + 1);
        }
    }
    if (mB > tp.best2B) {
        #pragma unroll
        for (int t = 0; t < 8; t++) {
            float2 e = env[t * 4 + pidx];
            upd(tp.bestB, tp.best2B, tp.idxB, d[t][2] + e.x, c_base + t * 8);
            upd(tp.bestB, tp.best2B, tp.idxB, d[t][3] + e.y, c_base + t * 8 + 1);
        }
    }
}

// ---------- tier 0: fp16 HMMA GEMM, pipelined epilogue (epi(s) under MMA(s+1)) ----------
__global__ __launch_bounds__(256, 2)
void vq_gemm1(const float* __restrict__ x) {
    extern __shared__ char dsm[];
    const int tid  = threadIdx.x;
    const int wid  = tid >> 5;
    const int lane = tid & 31;
    const uint32_t S = smem_u32(dsm);

    {
        const int rbase = blockIdx.x * GM;
        for (int idx = tid; idx < GM * DIMS; idx += 256) {
            int r = idx >> 6, d = idx & 63;
            float v = x[(size_t)(rbase + r) * DIMS + d];
            *(__half*)(dsm + r * SROW1 + 2 * d) = __float2half_rn(v);
        }
    }
    {   // prologue: super-chunk 0 B + en2
        const char* Bg = (const char*)g_bh;
        for (int c = tid; c < GNB * 8; c += 256) {
            int rowb = c >> 3, seg = c & 7;
            CP_ASYNC16(S + B1_OFF + rowb * SROW1 + seg * 16, Bg + rowb * 128 + seg * 16);
        }
        if (tid < 64) CP_ASYNC16(S + EN1_OFF + tid * 16, (const char*)g_en2 + tid * 16);
        CP_COMMIT();
        CP_WAIT(0);
    }
    __syncthreads();

    uint32_t af[4][4];
    {
        uint32_t a_base = S + (uint32_t)(wid * 16 + (lane & 15)) * SROW1 + (uint32_t)(lane >> 4) * 16;
        #pragma unroll
        for (int k = 0; k < 4; k++)
            LDSM4(af[k][0], af[k][1], af[k][2], af[k][3], a_base + k * 32);
    }

    const uint32_t n_part = (lane & 7) + ((lane >> 4) & 1) * 8;
    const uint32_t koff_b = ((lane >> 3) & 1) * 16;
    const int pidx = lane & 3;
    const int q    = lane >> 2;
    const int rowA_g = blockIdx.x * GM + wid * 16 + q;
    const int rowB_g = rowA_g + 8;

    Top2 tp;
    tp.bestA = tp.best2A = tp.bestB = tp.best2B = -FLT_MAX;
    tp.idxA = tp.idxB = 0;

    float d0[8][4], d1[8][4];

    for (int i = 0; i < NBIG; i++) {
        const int buf = i & 1;
        if (i + 1 < NBIG) {
            const char* Bg = (const char*)(g_bh + (size_t)(i + 1) * GNB * DIMS);
            uint32_t Bs = S + B1_OFF + (buf ^ 1) * B1_BYTES;
            for (int c = tid; c < GNB * 8; c += 256) {
                int rowb = c >> 3, seg = c & 7;
                CP_ASYNC16(Bs + rowb * SROW1 + seg * 16, Bg + rowb * 128 + seg * 16);
            }
            if (tid < 64)
                CP_ASYNC16(S + EN1_OFF + (buf ^ 1) * 1024 + tid * 16,
                           (const char*)(g_en2 + (i + 1) * GNB) + tid * 16);
            CP_COMMIT();
            CP_WAIT(1);
        } else {
            CP_WAIT(0);
        }
        __syncthreads();

        const uint32_t Bb = S + B1_OFF + buf * B1_BYTES;
        const float2* envb = (const float2*)(dsm + EN1_OFF + buf * 1024);
        const int ch = i * NSUB;

        // pipelined: MMA(s+1) issued before epilogue(s); epi fills MMA latency shadow
        mma_sub(d0, Bb,                 af, n_part, koff_b);
        mma_sub(d1, Bb + 1 * GN * SROW1, af, n_part, koff_b);
        epilogue(d0, envb,      pidx, ch + 0, tp, rowA_g, rowB_g);
        mma_sub(d0, Bb + 2 * GN * SROW1, af, n_part, koff_b);
        epilogue(d1, envb + 32, pidx, ch + 1, tp, rowA_g, rowB_g);
        mma_sub(d1, Bb + 3 * GN * SROW1, af, n_part, koff_b);
        epilogue(d0, envb + 64, pidx, ch + 2, tp, rowA_g, rowB_g);
        epilogue(d1, envb + 96, pidx, ch + 3, tp, rowA_g, rowB_g);

        __syncthreads();   // protect buf^1 (B + en2) before next prefetch overwrites
    }

    #pragma unroll
    for (int s = 1; s <= 2; s <<= 1) {
        float ob  = __shfl_xor_sync(0xffffffffu, tp.bestA,  s);
        float ob2 = __shfl_xor_sync(0xffffffffu, tp.best2A, s);
        int   oi  = __shfl_xor_sync(0xffffffffu, tp.idxA,   s);
        if (ob > tp.bestA) { tp.best2A = fmaxf(tp.bestA, ob2); tp.bestA = ob; tp.idxA = oi; }
        else               { tp.best2A = fmaxf(tp.best2A, ob); }
        ob  = __shfl_xor_sync(0xffffffffu, tp.bestB,  s);
        ob2 = __shfl_xor_sync(0xffffffffu, tp.best2B, s);
        oi  = __shfl_xor_sync(0xffffffffu, tp.idxB,   s);
        if (ob > tp.bestB) { tp.best2B = fmaxf(tp.bestB, ob2); tp.bestB = ob; tp.idxB = oi; }
        else               { tp.best2B = fmaxf(tp.best2B, ob); }
    }

    if (pidx == 0) {
        g_idx[rowA_g] = tp.idxA;
        g_idx[rowB_g] = tp.idxB;
        if (2.0f * (tp.bestA - tp.best2A) < TAU1) { int s = atomicAdd(&g_cnt, 1); g_list[s] = rowA_g; }
        if (2.0f * (tp.bestB - tp.best2B) < TAU1) { int s = atomicAdd(&g_cnt, 1); g_list[s] = rowB_g; }
    }
}

// ---------- candidate rescore: bit-exact reference emulation over candidate chunks ----------
__global__ __launch_bounds__(256)
void vq_cand(const float* __restrict__ x, const float* __restrict__ cb) {
    const int lane = threadIdx.x & 31;
    const int gw   = (blockIdx.x * blockDim.x + threadIdx.x) >> 5;
    const int nw   = (gridDim.x * blockDim.x) >> 5;
    const int cnt  = g_cnt;

    for (int i = gw; i < cnt; i += nw) {
        const int row = g_list[i];

        const float c0 = g_cmax[(size_t)lane * N_ROWS + row];
        const float c1 = g_cmax[(size_t)(lane + 32) * N_ROWS + row];
        float bm = fmaxf(c0, c1);
        #pragma unroll
        for (int s = 16; s > 0; s >>= 1)
            bm = fmaxf(bm, __shfl_xor_sync(0xffffffffu, bm, s));
        const float thr = bm - GTH;

        float xr[DIMS];
        {
            const float4* xp = (const float4*)(x + (size_t)row * DIMS);
            #pragma unroll
            for (int j = 0; j < DIMS / 4; j++) {
                float4 v = xp[j];
                xr[4 * j] = v.x; xr[4 * j + 1] = v.y;
                xr[4 * j + 2] = v.z; xr[4 * j + 3] = v.w;
            }
        }
        double xs;
        {
            float a = __ldg(x + (size_t)row * DIMS + 2 * lane);
            float b = __ldg(x + (size_t)row * DIMS + 2 * lane + 1);
            xs = (double)a * a + (double)b * b;
            #pragma unroll
            for (int off = 16; off > 0; off >>= 1)
                xs += __shfl_xor_sync(0xffffffffu, xs, off);
        }
        const float xnorm = (float)xs;

        float best = FLT_MAX;
        int   bi   = 0x7fffffff;
        for (int j = 0; j < NCHUNK; j++) {
            float cma = __shfl_sync(0xffffffffu, c0, j & 31);
            float cmb = __shfl_sync(0xffffffffu, c1, j & 31);
            float cm  = (j < 32) ? cma : cmb;
            if (cm < thr) continue;

            const int k0 = j * GN + lane;
            const int k1 = k0 + 32;
            const float4* e0 = (const float4*)(cb + (size_t)k0 * DIMS);
            const float4* e1 = (const float4*)(cb + (size_t)k1 * DIMS);
            float a0 = 0.0f, a1 = 0.0f;
            #pragma unroll
            for (int qd = 0; qd < DIMS / 4; qd++) {
                float4 E0 = e0[qd];
                float4 E1 = e1[qd];
                a0 = fmaf(xr[4 * qd + 0], E0.x, a0);
                a0 = fmaf(xr[4 * qd + 1], E0.y, a0);
                a0 = fmaf(xr[4 * qd + 2], E0.z, a0);
                a0 = fmaf(xr[4 * qd + 3], E0.w, a0);
                a1 = fmaf(xr[4 * qd + 0], E1.x, a1);
                a1 = fmaf(xr[4 * qd + 1], E1.y, a1);
                a1 = fmaf(xr[4 * qd + 2], E1.z, a1);
                a1 = fmaf(xr[4 * qd + 3], E1.w, a1);
            }
            float dd0 = (xnorm + __ldg(&g_enorm[k0])) - 2.0f * a0;
            float dd1 = (xnorm + __ldg(&g_enorm[k1])) - 2.0f * a1;
            if (dd0 < best) { best = dd0; bi = k0; }
            if (dd1 < best) { best = dd1; bi = k1; }
        }
        #pragma unroll
        for (int s = 1; s < 32; s <<= 1) {
            float ob = __shfl_xor_sync(0xffffffffu, best, s);
            int   oi = __shfl_xor_sync(0xffffffffu, bi,   s);
            if (ob < best || (ob == best && oi < bi)) { best = ob; bi = oi; }
        }
        if (lane == 0) g_idx[row] = bi;
    }
}

// ---------- epilogue: gather winner, straight-through output, loss partials ----------
__global__ __launch_bounds__(ETHREADS)
void vq_epi(const float* __restrict__ x, const float* __restrict__ y,
            const float* __restrict__ cb, float* __restrict__ out) {
    __shared__ float s_red[ETHREADS / 32];

    const int tid = threadIdx.x;
    const int row = blockIdx.x * ETHREADS + tid;
    const int bidx = g_idx[row];

    float ls = 0.f;
    const float4* xp = (const float4*)(x  + (size_t)row  * DIMS);
    const float4* yp = (const float4*)(y  + (size_t)row  * DIMS);
    const float4* ep = (const float4*)(cb + (size_t)bidx * DIMS);
    float4*       op = (float4*)(out + (size_t)row * DIMS);

    #pragma unroll
    for (int i = 0; i < DIMS / 4; i++) {
        float4 xv = xp[i];
        float4 yv = yp[i];
        float4 e  = ep[i];

        float d;
        d = e.x - xv.x; ls += d * d;  d = e.x - yv.x; ls += d * d;
        d = e.y - xv.y; ls += d * d;  d = e.y - yv.y; ls += d * d;
        d = e.z - xv.z; ls += d * d;  d = e.z - yv.z; ls += d * d;
        d = e.w - xv.w; ls += d * d;  d = e.w - yv.w; ls += d * d;

        float4 o;
        float a;
        a = xv.x + yv.x; o.x = a + (e.x - a);
        a = xv.y + yv.y; o.y = a + (e.y - a);
        a = xv.z + yv.z; o.z = a + (e.z - a);
        a = xv.w + yv.w; o.w = a + (e.w - a);
        op[i] = o;
    }

    #pragma unroll
    for (int off = 16; off > 0; off >>= 1)
        ls += __shfl_xor_sync(0xffffffffu, ls, off);
    if ((tid & 31) == 0) s_red[tid >> 5] = ls;
    __syncthreads();
    if (tid == 0) {
        float s = 0.f;
        #pragma unroll
        for (int w = 0; w < ETHREADS / 32; w++) s += s_red[w];
        g_bsum[blockIdx.x] = s;
    }
}

__global__ void vq_fin(float* __restrict__ out) {
    if (threadIdx.x == 0 && blockIdx.x == 0) {
        double acc = 0.0;
        for (int i = 0; i < EBLOCKS; i++) acc += (double)g_bsum[i];
        double loss = 1.25 * acc / (double)((size_t)N_ROWS * DIMS);
        out[(size_t)N_ROWS * DIMS] = (float)loss;
    }
}

extern "C" void kernel_launch(void* const* d_in, const int* in_sizes, int n_in,
                              void* d_out, int out_size) {
    const float* x  = (const float*)d_in[0];
    const float* y  = (const float*)d_in[1];
    const float* cb = (const float*)d_in[2];
    float* out = (float*)d_out;

    static int smem_set = 0;
    if (!smem_set) {
        cudaFuncSetAttribute(vq_gemm1, cudaFuncAttributeMaxDynamicSharedMemorySize, SMEM1_TOTAL);
        smem_set = 1;
    }

    vq_init<<<(KENT + 255) / 256, 256>>>(cb);
    vq_prep_cb<<<(KENT * DIMS / 4 + 255) / 256, 256>>>(cb);
    vq_gemm1<<<GBLOCKS, 256, SMEM1_TOTAL>>>(x);
    vq_cand<<<256, 256>>>(x, cb);
    vq_epi<<<EBLOCKS, ETHREADS>>>(x, y, cb, out);
    vq_fin<<<1, 1>>>(out);
}

// round 15
// speedup vs baseline: 1.0081x; 1.0081x over previous
#include <cuda_runtime.h>
#include <cuda_fp16.h>
#include <cstdint>
#include <cfloat>

// Problem constants
#define N_ROWS  131072
#define DIMS    64
#define KENT    4096
#define GM      128            // rows per CTA
#define GNB     256            // codes per pipeline super-chunk
#define NSUB    4              // 64-code sub-blocks per super-chunk
#define NBIG    (KENT / GNB)   // 16
#define GN2     32             // codes per cmax chunk (envelope granularity)
#define NCHUNK2 (KENT / GN2)   // 128
#define GBLOCKS (N_ROWS / GM)  // 1024
#define ETHREADS 256
#define EBLOCKS (N_ROWS / ETHREADS)
#define TAU1    0.03f          // fp16 dist margin -> flagged for exact candidate rescore
#define GTH     0.04f          // g-scale chunk-candidate slack (~25 sigma of per-code fp16 err)

// gemm1 smem
#define SROW1   144
#define A_BYTES (GM * SROW1)                  // 18432
#define B1_OFF  A_BYTES
#define B1_BYTES (GNB * SROW1)                // 36864 per buffer
#define EN1_OFF (B1_OFF + 2 * B1_BYTES)       // 92160
#define SMEM1_TOTAL (EN1_OFF + 2 * 1024)      // 94208

// Scratch
__device__ __half g_bh[(size_t)KENT * DIMS];            // fp16 codebook, 512 KB
__device__ float  g_cmax[(size_t)NCHUNK2 * N_ROWS];     // CHUNK-MAJOR [chunk][row], 67 MB
__device__ float  g_enorm[KENT];
__device__ float  g_en2[KENT];
__device__ float  g_bsum[EBLOCKS];
__device__ int    g_idx[N_ROWS];
__device__ int    g_list[N_ROWS];
__device__ int    g_cnt;

// ---------------- helpers ----------------
__device__ __forceinline__ uint32_t smem_u32(const void* p) {
    uint32_t a;
    asm("{ .reg .u64 t; cvta.to.shared.u64 t, %1; cvt.u32.u64 %0, t; }" : "=r"(a) : "l"(p));
    return a;
}
#define CP_ASYNC16(dst, src) \
    asm volatile("cp.async.cg.shared.global [%0], [%1], 16;" :: "r"(dst), "l"(src))
#define CP_COMMIT() asm volatile("cp.async.commit_group;" ::: "memory")
#define CP_WAIT(n)  asm volatile("cp.async.wait_group %0;" :: "n"(n) : "memory")

#define LDSM4(r0, r1, r2, r3, a) \
    asm volatile("ldmatrix.sync.aligned.m8n8.x4.shared.b16 {%0,%1,%2,%3}, [%4];" \
        : "=r"(r0), "=r"(r1), "=r"(r2), "=r"(r3) : "r"(a))

// accumulate form
#define MMA16816(d, a, b0_, b1_) \
    asm volatile("mma.sync.aligned.m16n8k16.row.col.f32.f16.f16.f32 " \
        "{%0,%1,%2,%3}, {%4,%5,%6,%7}, {%8,%9}, {%0,%1,%2,%3};" \
        : "+f"((d)[0]), "+f"((d)[1]), "+f"((d)[2]), "+f"((d)[3]) \
        : "r"((a)[0]), "r"((a)[1]), "r"((a)[2]), "r"((a)[3]), "r"(b0_), "r"(b1_))

// init form: d = a*b + 0 (no zero-MOV per accumulator needed)
#define MMA16816_Z(d, a, b0_, b1_) \
    asm volatile("mma.sync.aligned.m16n8k16.row.col.f32.f16.f16.f32 " \
        "{%0,%1,%2,%3}, {%4,%5,%6,%7}, {%8,%9}, {%10,%10,%10,%10};" \
        : "=f"((d)[0]), "=f"((d)[1]), "=f"((d)[2]), "=f"((d)[3]) \
        : "r"((a)[0]), "r"((a)[1]), "r"((a)[2]), "r"((a)[3]), "r"(b0_), "r"(b1_), "f"(0.0f))

__device__ __forceinline__ void upd(float& b, float& b2, int& id, float g, int c) {
    if (g > b) { b2 = b; b = g; id = c; }
    else if (g > b2) { b2 = g; }
}

// ---------- kernel 0: norms (fp64->fp32), -en/2, counter reset ----------
__global__ void vq_init(const float* __restrict__ cb) {
    int k = blockIdx.x * blockDim.x + threadIdx.x;
    if (k == 0) g_cnt = 0;
    if (k < KENT) {
        const float4* p = (const float4*)(cb + (size_t)k * DIMS);
        double s = 0.0;
        #pragma unroll
        for (int i = 0; i < DIMS / 4; i++) {
            float4 v = p[i];
            s += (double)v.x * v.x + (double)v.y * v.y
               + (double)v.z * v.z + (double)v.w * v.w;
        }
        g_enorm[k] = (float)s;
        g_en2[k]   = (float)(-0.5 * s);
    }
}

// ---------- prep: cb -> fp16 ----------
__global__ void vq_prep_cb(const float* __restrict__ cb) {
    int i = blockIdx.x * blockDim.x + threadIdx.x;
    if (i < KENT * DIMS / 4) {
        float4 v = ((const float4*)cb)[i];
        __half2* o = (__half2*)(g_bh + (size_t)i * 4);
        o[0] = __floats2half2_rn(v.x, v.y);
        o[1] = __floats2half2_rn(v.z, v.w);
    }
}

// ---------- tier 0: fp16 HMMA GEMM, n-split warps, lazy top-2 + 32-code cmax ----------
// warp (mg, nh): rows mg*32..+31, codes nh*32 of each 64-code sub-block.
__global__ __launch_bounds__(256, 2)
void vq_gemm1(const float* __restrict__ x) {
    extern __shared__ char dsm[];
    const int tid  = threadIdx.x;
    const int wid  = tid >> 5;
    const int lane = tid & 31;
    const int mg   = wid >> 1;
    const int nh   = wid & 1;
    const uint32_t S = smem_u32(dsm);

    {
        const int rbase = blockIdx.x * GM;
        for (int idx = tid; idx < GM * DIMS; idx += 256) {
            int r = idx >> 6, d = idx & 63;
            float v = x[(size_t)(rbase + r) * DIMS + d];
            *(__half*)(dsm + r * SROW1 + 2 * d) = __float2half_rn(v);
        }
    }
    {   // prologue: super-chunk 0 B + en2
        const char* Bg = (const char*)g_bh;
        for (int c = tid; c < GNB * 8; c += 256) {
            int rowb = c >> 3, seg = c & 7;
            CP_ASYNC16(S + B1_OFF + rowb * SROW1 + seg * 16, Bg + rowb * 128 + seg * 16);
        }
        if (tid < 64) CP_ASYNC16(S + EN1_OFF + tid * 16, (const char*)g_en2 + tid * 16);
        CP_COMMIT();
        CP_WAIT(0);
    }
    __syncthreads();

    // hoist A fragments: 2 m-tiles x 4 k-steps
    uint32_t af[2][4][4];
    #pragma unroll
    for (int mt = 0; mt < 2; mt++) {
        uint32_t a_base = S + (uint32_t)(mg * 32 + mt * 16 + (lane & 15)) * SROW1
                        + (uint32_t)(lane >> 4) * 16;
        #pragma unroll
        for (int k = 0; k < 4; k++)
            LDSM4(af[mt][k][0], af[mt][k][1], af[mt][k][2], af[mt][k][3], a_base + k * 32);
    }

    const uint32_t n_part = (lane & 7) + ((lane >> 4) & 1) * 8;
    const uint32_t koff_b = ((lane >> 3) & 1) * 16;
    const int c4 = lane & 3;       // quad column id
    const int q  = lane >> 2;      // quad row id
    const int rowbase = blockIdx.x * GM + mg * 32;

    float tb[4], tb2[4];           // per-row-identity top-2 (rids: q, q+8, 16+q, 24+q)
    int   tix[4];
    #pragma unroll
    for (int r = 0; r < 4; r++) { tb[r] = -FLT_MAX; tb2[r] = -FLT_MAX; tix[r] = 0; }

    for (int i = 0; i < NBIG; i++) {
        const int buf = i & 1;
        if (i + 1 < NBIG) {
            const char* Bg = (const char*)(g_bh + (size_t)(i + 1) * GNB * DIMS);
            uint32_t Bs = S + B1_OFF + (buf ^ 1) * B1_BYTES;
            for (int c = tid; c < GNB * 8; c += 256) {
                int rowb = c >> 3, seg = c & 7;
                CP_ASYNC16(Bs + rowb * SROW1 + seg * 16, Bg + rowb * 128 + seg * 16);
            }
            if (tid < 64)
                CP_ASYNC16(S + EN1_OFF + (buf ^ 1) * 1024 + tid * 16,
                           (const char*)(g_en2 + (i + 1) * GNB) + tid * 16);
            CP_COMMIT();
            CP_WAIT(1);
        } else {
            CP_WAIT(0);
        }
        __syncthreads();

        const uint32_t Bb = S + B1_OFF + buf * B1_BYTES;
        const float2* envb = (const float2*)(dsm + EN1_OFF + buf * 1024);

        #pragma unroll
        for (int s = 0; s < NSUB; s++) {
            // warp's 32-code half of sub-block s
            const uint32_t Bs = Bb + (uint32_t)(s * 64 + nh * 32) * SROW1;
            float d[2][4][4];
            {   // k = 0: init form (no accumulator zeroing)
                #pragma unroll
                for (int jp = 0; jp < 2; jp++) {
                    uint32_t b0, b1, b2, b3;
                    LDSM4(b0, b1, b2, b3, Bs + (16 * jp + n_part) * SROW1 + koff_b);
                    MMA16816_Z(d[0][2 * jp],     af[0][0], b0, b1);
                    MMA16816_Z(d[0][2 * jp + 1], af[0][0], b2, b3);
                    MMA16816_Z(d[1][2 * jp],     af[1][0], b0, b1);
                    MMA16816_Z(d[1][2 * jp + 1], af[1][0], b2, b3);
                }
            }
            #pragma unroll
            for (int k = 1; k < 4; k++) {
                #pragma unroll
                for (int jp = 0; jp < 2; jp++) {
                    uint32_t b0, b1, b2, b3;
                    LDSM4(b0, b1, b2, b3, Bs + (16 * jp + n_part) * SROW1 + k * 32 + koff_b);
                    MMA16816(d[0][2 * jp],     af[0][k], b0, b1);
                    MMA16816(d[0][2 * jp + 1], af[0][k], b2, b3);
                    MMA16816(d[1][2 * jp],     af[1][k], b0, b1);
                    MMA16816(d[1][2 * jp + 1], af[1][k], b2, b3);
                }
            }

            // epilogue: g = d + en2; balanced trees per row identity
            const float2* env = envb + s * 32 + nh * 16;
            float2 e0 = env[0 * 4 + c4], e1 = env[1 * 4 + c4];
            float2 e2 = env[2 * 4 + c4], e3 = env[3 * 4 + c4];

            float m[4];
            #pragma unroll
            for (int rid = 0; rid < 4; rid++) {
                const int mt = rid >> 1, hp = (rid & 1) * 2;
                float t0 = fmaxf(fmaxf(d[mt][0][hp] + e0.x, d[mt][0][hp + 1] + e0.y),
                                 fmaxf(d[mt][1][hp] + e1.x, d[mt][1][hp + 1] + e1.y));
                float t1 = fmaxf(fmaxf(d[mt][2][hp] + e2.x, d[mt][2][hp + 1] + e2.y),
                                 fmaxf(d[mt][3][hp] + e3.x, d[mt][3][hp + 1] + e3.y));
                m[rid] = fmaxf(t0, t1);
            }
            #pragma unroll
            for (int rid = 0; rid < 4; rid++) {
                m[rid] = fmaxf(m[rid], __shfl_xor_sync(0xffffffffu, m[rid], 1));
                m[rid] = fmaxf(m[rid], __shfl_xor_sync(0xffffffffu, m[rid], 2));
            }

            const int chunk2 = (i * NSUB + s) * 2 + nh;
            if (c4 == 0) {
                float* gc = g_cmax + (size_t)chunk2 * N_ROWS + rowbase;
                gc[q]      = m[0];
                gc[q + 8]  = m[1];
                gc[q + 16] = m[2];
                gc[q + 24] = m[3];
            }

            const int cbase = (i * NSUB + s) * 64 + nh * 32 + c4 * 2;
            #pragma unroll
            for (int rid = 0; rid < 4; rid++) {
                if (m[rid] > tb2[rid]) {
                    const int mt = rid >> 1, hp = (rid & 1) * 2;
                    upd(tb[rid], tb2[rid], tix[rid], d[mt][0][hp]     + e0.x, cbase);
                    upd(tb[rid], tb2[rid], tix[rid], d[mt][0][hp + 1] + e0.y, cbase + 1);
                    upd(tb[rid], tb2[rid], tix[rid], d[mt][1][hp]     + e1.x, cbase + 8);
                    upd(tb[rid], tb2[rid], tix[rid], d[mt][1][hp + 1] + e1.y, cbase + 9);
                    upd(tb[rid], tb2[rid], tix[rid], d[mt][2][hp]     + e2.x, cbase + 16);
                    upd(tb[rid], tb2[rid], tix[rid], d[mt][2][hp + 1] + e2.y, cbase + 17);
                    upd(tb[rid], tb2[rid], tix[rid], d[mt][3][hp]     + e3.x, cbase + 24);
                    upd(tb[rid], tb2[rid], tix[rid], d[mt][3][hp + 1] + e3.y, cbase + 25);
                }
            }
        }
        __syncthreads();   // protect buf^1 (B + en2) before next prefetch overwrites
    }

    // quad merge per row identity
    #pragma unroll
    for (int rid = 0; rid < 4; rid++) {
        #pragma unroll
        for (int s = 1; s <= 2; s <<= 1) {
            float ob  = __shfl_xor_sync(0xffffffffu, tb[rid],  s);
            float ob2 = __shfl_xor_sync(0xffffffffu, tb2[rid], s);
            int   oi  = __shfl_xor_sync(0xffffffffu, tix[rid], s);
            if (ob > tb[rid]) { tb2[rid] = fmaxf(tb[rid], ob2); tb[rid] = ob; tix[rid] = oi; }
            else              { tb2[rid] = fmaxf(tb2[rid], ob); }
        }
    }

    // cross-half (nh) merge via smem (reuse A region — A no longer needed)
    float* s_b  = (float*)dsm;                 // [128][2]
    float* s_b2 = (float*)(dsm + 1024);        // [128][2]
    int*   s_ix = (int*)(dsm + 2048);          // [128][2]
    if (c4 == 0) {
        const int roff[4] = {0, 8, 16, 24};
        #pragma unroll
        for (int rid = 0; rid < 4; rid++) {
            int rl = mg * 32 + q + roff[rid];
            s_b [rl * 2 + nh] = tb[rid];
            s_b2[rl * 2 + nh] = tb2[rid];
            s_ix[rl * 2 + nh] = tix[rid];
        }
    }
    __syncthreads();
    if (tid < GM) {
        float bA = s_b[tid * 2],  bB = s_b[tid * 2 + 1];
        float aA = s_b2[tid * 2], aB = s_b2[tid * 2 + 1];
        int   iA = s_ix[tid * 2], iB = s_ix[tid * 2 + 1];
        float best, best2; int idx;
        if (bA >= bB) { best = bA; idx = iA; best2 = fmaxf(aA, bB); }
        else          { best = bB; idx = iB; best2 = fmaxf(aB, bA); }
        const int row = blockIdx.x * GM + tid;
        g_idx[row] = idx;
        if (2.0f * (best - best2) < TAU1) { int s = atomicAdd(&g_cnt, 1); g_list[s] = row; }
    }
}

// ---------- candidate rescore: bit-exact reference emulation over candidate chunks ----------
// 128 chunks of 32 codes; one code per lane per candidate chunk.
__global__ __launch_bounds__(256)
void vq_cand(const float* __restrict__ x, const float* __restrict__ cb) {
    __shared__ float s_env[8][NCHUNK2];
    const int lane  = threadIdx.x & 31;
    const int wslot = threadIdx.x >> 5;
    const int gw    = (blockIdx.x * blockDim.x + threadIdx.x) >> 5;
    const int nw    = (gridDim.x * blockDim.x) >> 5;
    const int cnt   = g_cnt;

    for (int i = gw; i < cnt; i += nw) {
        const int row = g_list[i];

        __syncwarp();
        const float c0 = g_cmax[(size_t)lane * N_ROWS + row];
        const float c1 = g_cmax[(size_t)(lane + 32) * N_ROWS + row];
        const float c2 = g_cmax[(size_t)(lane + 64) * N_ROWS + row];
        const float c3 = g_cmax[(size_t)(lane + 96) * N_ROWS + row];
        s_env[wslot][lane]      = c0;
        s_env[wslot][lane + 32] = c1;
        s_env[wslot][lane + 64] = c2;
        s_env[wslot][lane + 96] = c3;
        __syncwarp();

        float bm = fmaxf(fmaxf(c0, c1), fmaxf(c2, c3));
        #pragma unroll
        for (int s = 16; s > 0; s >>= 1)
            bm = fmaxf(bm, __shfl_xor_sync(0xffffffffu, bm, s));
        const float thr = bm - GTH;

        float xr[DIMS];
        {
            const float4* xp = (const float4*)(x + (size_t)row * DIMS);
            #pragma unroll
            for (int j = 0; j < DIMS / 4; j++) {
                float4 v = xp[j];
                xr[4 * j] = v.x; xr[4 * j + 1] = v.y;
                xr[4 * j + 2] = v.z; xr[4 * j + 3] = v.w;
            }
        }
        double xs;
        {
            float a = __ldg(x + (size_t)row * DIMS + 2 * lane);
            float b = __ldg(x + (size_t)row * DIMS + 2 * lane + 1);
            xs = (double)a * a + (double)b * b;
            #pragma unroll
            for (int off = 16; off > 0; off >>= 1)
                xs += __shfl_xor_sync(0xffffffffu, xs, off);
        }
        const float xnorm = (float)xs;

        float best = FLT_MAX;
        int   bi   = 0x7fffffff;
        for (int j = 0; j < NCHUNK2; j++) {
            if (s_env[wslot][j] < thr) continue;

            const int k = j * GN2 + lane;
            const float4* e4 = (const float4*)(cb + (size_t)k * DIMS);
            float acc = 0.0f;
            #pragma unroll
            for (int qd = 0; qd < DIMS / 4; qd++) {
                float4 E = e4[qd];
                acc = fmaf(xr[4 * qd + 0], E.x, acc);
                acc = fmaf(xr[4 * qd + 1], E.y, acc);
                acc = fmaf(xr[4 * qd + 2], E.z, acc);
                acc = fmaf(xr[4 * qd + 3], E.w, acc);
            }
            float dd = (xnorm + __ldg(&g_enorm[k])) - 2.0f * acc;
            if (dd < best) { best = dd; bi = k; }   // ascending j => first-min per lane
        }
        #pragma unroll
        for (int s = 1; s < 32; s <<= 1) {
            float ob = __shfl_xor_sync(0xffffffffu, best, s);
            int   oi = __shfl_xor_sync(0xffffffffu, bi,   s);
            if (ob < best || (ob == best && oi < bi)) { best = ob; bi = oi; }
        }
        if (lane == 0) g_idx[row] = bi;
    }
}

// ---------- epilogue: gather winner, straight-through output, loss partials ----------
__global__ __launch_bounds__(ETHREADS)
void vq_epi(const float* __restrict__ x, const float* __restrict__ y,
            const float* __restrict__ cb, float* __restrict__ out) {
    __shared__ float s_red[ETHREADS / 32];

    const int tid = threadIdx.x;
    const int row = blockIdx.x * ETHREADS + tid;
    const int bidx = g_idx[row];

    float ls = 0.f;
    const float4* xp = (const float4*)(x  + (size_t)row  * DIMS);
    const float4* yp = (const float4*)(y  + (size_t)row  * DIMS);
    const float4* ep = (const float4*)(cb + (size_t)bidx * DIMS);
    float4*       op = (float4*)(out + (size_t)row * DIMS);

    #pragma unroll
    for (int i = 0; i < DIMS / 4; i++) {
        float4 xv = xp[i];
        float4 yv = yp[i];
        float4 e  = ep[i];

        float d;
        d = e.x - xv.x; ls += d * d;  d = e.x - yv.x; ls += d * d;
        d = e.y - xv.y; ls += d * d;  d = e.y - yv.y; ls += d * d;
        d = e.z - xv.z; ls += d * d;  d = e.z - yv.z; ls += d * d;
        d = e.w - xv.w; ls += d * d;  d = e.w - yv.w; ls += d * d;

        float4 o;
        float a;
        a = xv.x + yv.x; o.x = a + (e.x - a);
        a = xv.y + yv.y; o.y = a + (e.y - a);
        a = xv.z + yv.z; o.z = a + (e.z - a);
        a = xv.w + yv.w; o.w = a + (e.w - a);
        op[i] = o;
    }

    #pragma unroll
    for (int off = 16; off > 0; off >>= 1)
        ls += __shfl_xor_sync(0xffffffffu, ls, off);
    if ((tid & 31) == 0) s_red[tid >> 5] = ls;
    __syncthreads();
    if (tid == 0) {
        float s = 0.f;
        #pragma unroll
        for (int w = 0; w < ETHREADS / 32; w++) s += s_red[w];
        g_bsum[blockIdx.x] = s;
    }
}

__global__ void vq_fin(float* __restrict__ out) {
    if (threadIdx.x == 0 && blockIdx.x == 0) {
        double acc = 0.0;
        for (int i = 0; i < EBLOCKS; i++) acc += (double)g_bsum[i];
        double loss = 1.25 * acc / (double)((size_t)N_ROWS * DIMS);
        out[(size_t)N_ROWS * DIMS] = (float)loss;
    }
}

extern "C" void kernel_launch(void* const* d_in, const int* in_sizes, int n_in,
                              void* d_out, int out_size) {
    const float* x  = (const float*)d_in[0];
    const float* y  = (const float*)d_in[1];
    const float* cb = (const float*)d_in[2];
    float* out = (float*)d_out;

    static int smem_set = 0;
    if (!smem_set) {
        cudaFuncSetAttribute(vq_gemm1, cudaFuncAttributeMaxDynamicSharedMemorySize, SMEM1_TOTAL);
        smem_set = 1;
    }

    vq_init<<<(KENT + 255) / 256, 256>>>(cb);
    vq_prep_cb<<<(KENT * DIMS / 4 + 255) / 256, 256>>>(cb);
    vq_gemm1<<<GBLOCKS, 256, SMEM1_TOTAL>>>(x);
    vq_cand<<<256, 256>>>(x, cb);
    vq_epi<<<EBLOCKS, ETHREADS>>>(x, y, cb, out);
    vq_fin<<<1, 1>>>(out);
}

// round 16
// speedup vs baseline: 1.1711x; 1.1617x over previous
#include <cuda_runtime.h>
#include <cuda_fp16.h>
#include <cstdint>
#include <cfloat>

// Problem constants
#define N_ROWS  131072
#define DIMS    64
#define KENT    4096
#define GM      128            // rows per CTA
#define GNB     128            // codes per pipeline super-chunk
#define NSTEP   4              // 32-code steps per super-chunk
#define NBIG    (KENT / GNB)   // 32
#define GN2     32             // codes per cmax chunk (envelope granularity)
#define NCHUNK2 (KENT / GN2)   // 128
#define GBLOCKS (N_ROWS / GM)  // 1024
#define ETHREADS 256
#define EBLOCKS (N_ROWS / ETHREADS)
#define TAU1    0.03f          // fp16 dist margin -> flagged for exact candidate rescore
#define GTH     0.04f          // g-scale chunk-candidate slack (~25 sigma)

// gemm1 smem
#define SROW1   144
#define A_BYTES (GM * SROW1)                  // 18432
#define B1_OFF  A_BYTES
#define B1_BYTES (GNB * SROW1)                // 18432 per buffer
#define EN1_OFF (B1_OFF + 2 * B1_BYTES)       // 55296
#define SMEM1_TOTAL (EN1_OFF + 2 * 512)       // 56320

// Scratch
__device__ __half g_bh[(size_t)KENT * DIMS];            // fp16 codebook, 512 KB
__device__ float  g_cmax[(size_t)NCHUNK2 * N_ROWS];     // CHUNK-MAJOR [chunk][row], 67 MB
__device__ float  g_enorm[KENT];
__device__ float  g_en2[KENT];
__device__ float  g_bsum[EBLOCKS];
__device__ int    g_idx[N_ROWS];
__device__ int    g_list[N_ROWS];
__device__ int    g_cnt;

// ---------------- helpers ----------------
__device__ __forceinline__ uint32_t smem_u32(const void* p) {
    uint32_t a;
    asm("{ .reg .u64 t; cvta.to.shared.u64 t, %1; cvt.u32.u64 %0, t; }" : "=r"(a) : "l"(p));
    return a;
}
#define CP_ASYNC16(dst, src) \
    asm volatile("cp.async.cg.shared.global [%0], [%1], 16;" :: "r"(dst), "l"(src))
#define CP_COMMIT() asm volatile("cp.async.commit_group;" ::: "memory")
#define CP_WAIT(n)  asm volatile("cp.async.wait_group %0;" :: "n"(n) : "memory")

#define LDSM4(r0, r1, r2, r3, a) \
    asm volatile("ldmatrix.sync.aligned.m8n8.x4.shared.b16 {%0,%1,%2,%3}, [%4];" \
        : "=r"(r0), "=r"(r1), "=r"(r2), "=r"(r3) : "r"(a))

// accumulate form
#define MMA16816(d, a, b0_, b1_) \
    asm volatile("mma.sync.aligned.m16n8k16.row.col.f32.f16.f16.f32 " \
        "{%0,%1,%2,%3}, {%4,%5,%6,%7}, {%8,%9}, {%0,%1,%2,%3};" \
        : "+f"((d)[0]), "+f"((d)[1]), "+f"((d)[2]), "+f"((d)[3]) \
        : "r"((a)[0]), "r"((a)[1]), "r"((a)[2]), "r"((a)[3]), "r"(b0_), "r"(b1_))

// init form: d = a*b + 0
#define MMA16816_Z(d, a, b0_, b1_) \
    asm volatile("mma.sync.aligned.m16n8k16.row.col.f32.f16.f16.f32 " \
        "{%0,%1,%2,%3}, {%4,%5,%6,%7}, {%8,%9}, {%10,%10,%10,%10};" \
        : "=f"((d)[0]), "=f"((d)[1]), "=f"((d)[2]), "=f"((d)[3]) \
        : "r"((a)[0]), "r"((a)[1]), "r"((a)[2]), "r"((a)[3]), "r"(b0_), "r"(b1_), "f"(0.0f))

__device__ __forceinline__ void upd(float& b, float& b2, int& id, float g, int c) {
    if (g > b) { b2 = b; b = g; id = c; }
    else if (g > b2) { b2 = g; }
}

// ---------- kernel 0: norms (fp64->fp32), -en/2, counter reset ----------
__global__ void vq_init(const float* __restrict__ cb) {
    int k = blockIdx.x * blockDim.x + threadIdx.x;
    if (k == 0) g_cnt = 0;
    if (k < KENT) {
        const float4* p = (const float4*)(cb + (size_t)k * DIMS);
        double s = 0.0;
        #pragma unroll
        for (int i = 0; i < DIMS / 4; i++) {
            float4 v = p[i];
            s += (double)v.x * v.x + (double)v.y * v.y
               + (double)v.z * v.z + (double)v.w * v.w;
        }
        g_enorm[k] = (float)s;
        g_en2[k]   = (float)(-0.5 * s);
    }
}

// ---------- prep: cb -> fp16 ----------
__global__ void vq_prep_cb(const float* __restrict__ cb) {
    int i = blockIdx.x * blockDim.x + threadIdx.x;
    if (i < KENT * DIMS / 4) {
        float4 v = ((const float4*)cb)[i];
        __half2* o = (__half2*)(g_bh + (size_t)i * 4);
        o[0] = __floats2half2_rn(v.x, v.y);
        o[1] = __floats2half2_rn(v.z, v.w);
    }
}

// ---------- tier 0: fp16 HMMA GEMM, 32-code steps, 3 CTAs/SM ----------
// warp wid: rows wid*16..+15, full 32-code width per step.
__global__ __launch_bounds__(256, 3)
void vq_gemm1(const float* __restrict__ x) {
    extern __shared__ char dsm[];
    const int tid  = threadIdx.x;
    const int wid  = tid >> 5;
    const int lane = tid & 31;
    const uint32_t S = smem_u32(dsm);

    {
        const int rbase = blockIdx.x * GM;
        for (int idx = tid; idx < GM * DIMS; idx += 256) {
            int r = idx >> 6, d = idx & 63;
            float v = x[(size_t)(rbase + r) * DIMS + d];
            *(__half*)(dsm + r * SROW1 + 2 * d) = __float2half_rn(v);
        }
    }
    {   // prologue: super-chunk 0 B + en2
        const char* Bg = (const char*)g_bh;
        for (int c = tid; c < GNB * 8; c += 256) {
            int rowb = c >> 3, seg = c & 7;
            CP_ASYNC16(S + B1_OFF + rowb * SROW1 + seg * 16, Bg + rowb * 128 + seg * 16);
        }
        if (tid < 32) CP_ASYNC16(S + EN1_OFF + tid * 16, (const char*)g_en2 + tid * 16);
        CP_COMMIT();
        CP_WAIT(0);
    }
    __syncthreads();

    uint32_t af[4][4];
    {
        uint32_t a_base = S + (uint32_t)(wid * 16 + (lane & 15)) * SROW1 + (uint32_t)(lane >> 4) * 16;
        #pragma unroll
        for (int k = 0; k < 4; k++)
            LDSM4(af[k][0], af[k][1], af[k][2], af[k][3], a_base + k * 32);
    }

    const uint32_t n_part = (lane & 7) + ((lane >> 4) & 1) * 8;
    const uint32_t koff_b = ((lane >> 3) & 1) * 16;
    const int c4 = lane & 3;
    const int q  = lane >> 2;
    const int rowA_g = blockIdx.x * GM + wid * 16 + q;
    const int rowB_g = rowA_g + 8;

    float bestA = -FLT_MAX, best2A = -FLT_MAX;
    float bestB = -FLT_MAX, best2B = -FLT_MAX;
    int   idxA = 0, idxB = 0;

    for (int i = 0; i < NBIG; i++) {
        const int buf = i & 1;
        if (i + 1 < NBIG) {
            const char* Bg = (const char*)(g_bh + (size_t)(i + 1) * GNB * DIMS);
            uint32_t Bs = S + B1_OFF + (buf ^ 1) * B1_BYTES;
            for (int c = tid; c < GNB * 8; c += 256) {
                int rowb = c >> 3, seg = c & 7;
                CP_ASYNC16(Bs + rowb * SROW1 + seg * 16, Bg + rowb * 128 + seg * 16);
            }
            if (tid < 32)
                CP_ASYNC16(S + EN1_OFF + (buf ^ 1) * 512 + tid * 16,
                           (const char*)(g_en2 + (i + 1) * GNB) + tid * 16);
            CP_COMMIT();
            CP_WAIT(1);
        } else {
            CP_WAIT(0);
        }
        __syncthreads();

        const uint32_t Bb = S + B1_OFF + buf * B1_BYTES;
        const float2* envb = (const float2*)(dsm + EN1_OFF + buf * 512);

        #pragma unroll
        for (int s = 0; s < NSTEP; s++) {
            const uint32_t Bs = Bb + (uint32_t)(s * GN2) * SROW1;
            float d[4][4];
            {   // k = 0: init form (no accumulator zeroing)
                #pragma unroll
                for (int jp = 0; jp < 2; jp++) {
                    uint32_t b0, b1, b2, b3;
                    LDSM4(b0, b1, b2, b3, Bs + (16 * jp + n_part) * SROW1 + koff_b);
                    MMA16816_Z(d[2 * jp],     af[0], b0, b1);
                    MMA16816_Z(d[2 * jp + 1], af[0], b2, b3);
                }
            }
            #pragma unroll
            for (int k = 1; k < 4; k++) {
                #pragma unroll
                for (int jp = 0; jp < 2; jp++) {
                    uint32_t b0, b1, b2, b3;
                    LDSM4(b0, b1, b2, b3, Bs + (16 * jp + n_part) * SROW1 + k * 32 + koff_b);
                    MMA16816(d[2 * jp],     af[k], b0, b1);
                    MMA16816(d[2 * jp + 1], af[k], b2, b3);
                }
            }

            // epilogue: g = d + en2; lazy top-2; 32-code cmax
            const float2* env = envb + s * 16;       // 16 float2 per 32-code step
            float2 e0 = env[0 * 4 + c4], e1 = env[1 * 4 + c4];
            float2 e2 = env[2 * 4 + c4], e3 = env[3 * 4 + c4];

            float mA = fmaxf(fmaxf(d[0][0] + e0.x, d[0][1] + e0.y),
                             fmaxf(d[1][0] + e1.x, d[1][1] + e1.y));
            mA = fmaxf(mA, fmaxf(fmaxf(d[2][0] + e2.x, d[2][1] + e2.y),
                                 fmaxf(d[3][0] + e3.x, d[3][1] + e3.y)));
            float mB = fmaxf(fmaxf(d[0][2] + e0.x, d[0][3] + e0.y),
                             fmaxf(d[1][2] + e1.x, d[1][3] + e1.y));
            mB = fmaxf(mB, fmaxf(fmaxf(d[2][2] + e2.x, d[2][3] + e2.y),
                                 fmaxf(d[3][2] + e3.x, d[3][3] + e3.y)));

            mA = fmaxf(mA, __shfl_xor_sync(0xffffffffu, mA, 1));
            mA = fmaxf(mA, __shfl_xor_sync(0xffffffffu, mA, 2));
            mB = fmaxf(mB, __shfl_xor_sync(0xffffffffu, mB, 1));
            mB = fmaxf(mB, __shfl_xor_sync(0xffffffffu, mB, 2));

            const int chunk2 = i * NSTEP + s;
            if (c4 == 0) {
                g_cmax[(size_t)chunk2 * N_ROWS + rowA_g] = mA;
                g_cmax[(size_t)chunk2 * N_ROWS + rowB_g] = mB;
            }

            const int cbase = chunk2 * GN2 + c4 * 2;
            if (mA > best2A) {
                upd(bestA, best2A, idxA, d[0][0] + e0.x, cbase);
                upd(bestA, best2A, idxA, d[0][1] + e0.y, cbase + 1);
                upd(bestA, best2A, idxA, d[1][0] + e1.x, cbase + 8);
                upd(bestA, best2A, idxA, d[1][1] + e1.y, cbase + 9);
                upd(bestA, best2A, idxA, d[2][0] + e2.x, cbase + 16);
                upd(bestA, best2A, idxA, d[2][1] + e2.y, cbase + 17);
                upd(bestA, best2A, idxA, d[3][0] + e3.x, cbase + 24);
                upd(bestA, best2A, idxA, d[3][1] + e3.y, cbase + 25);
            }
            if (mB > best2B) {
                upd(bestB, best2B, idxB, d[0][2] + e0.x, cbase);
                upd(bestB, best2B, idxB, d[0][3] + e0.y, cbase + 1);
                upd(bestB, best2B, idxB, d[1][2] + e1.x, cbase + 8);
                upd(bestB, best2B, idxB, d[1][3] + e1.y, cbase + 9);
                upd(bestB, best2B, idxB, d[2][2] + e2.x, cbase + 16);
                upd(bestB, best2B, idxB, d[2][3] + e2.y, cbase + 17);
                upd(bestB, best2B, idxB, d[3][2] + e3.x, cbase + 24);
                upd(bestB, best2B, idxB, d[3][3] + e3.y, cbase + 25);
            }
        }
        __syncthreads();   // protect buf^1 (B + en2) before next prefetch overwrites
    }

    #pragma unroll
    for (int s = 1; s <= 2; s <<= 1) {
        float ob  = __shfl_xor_sync(0xffffffffu, bestA,  s);
        float ob2 = __shfl_xor_sync(0xffffffffu, best2A, s);
        int   oi  = __shfl_xor_sync(0xffffffffu, idxA,   s);
        if (ob > bestA) { best2A = fmaxf(bestA, ob2); bestA = ob; idxA = oi; }
        else            { best2A = fmaxf(best2A, ob); }
        ob  = __shfl_xor_sync(0xffffffffu, bestB,  s);
        ob2 = __shfl_xor_sync(0xffffffffu, best2B, s);
        oi  = __shfl_xor_sync(0xffffffffu, idxB,   s);
        if (ob > bestB) { best2B = fmaxf(bestB, ob2); bestB = ob; idxB = oi; }
        else            { best2B = fmaxf(best2B, ob); }
    }

    if (c4 == 0) {
        g_idx[rowA_g] = idxA;
        g_idx[rowB_g] = idxB;
        if (2.0f * (bestA - best2A) < TAU1) { int s = atomicAdd(&g_cnt, 1); g_list[s] = rowA_g; }
        if (2.0f * (bestB - best2B) < TAU1) { int s = atomicAdd(&g_cnt, 1); g_list[s] = rowB_g; }
    }
}

// ---------- candidate rescore: bit-exact reference emulation over candidate chunks ----------
// 128 chunks of 32 codes; one code per lane per candidate chunk. (validated in R15)
__global__ __launch_bounds__(256)
void vq_cand(const float* __restrict__ x, const float* __restrict__ cb) {
    __shared__ float s_env[8][NCHUNK2];
    const int lane  = threadIdx.x & 31;
    const int wslot = threadIdx.x >> 5;
    const int gw    = (blockIdx.x * blockDim.x + threadIdx.x) >> 5;
    const int nw    = (gridDim.x * blockDim.x) >> 5;
    const int cnt   = g_cnt;

    for (int i = gw; i < cnt; i += nw) {
        const int row = g_list[i];

        __syncwarp();
        const float c0 = g_cmax[(size_t)lane * N_ROWS + row];
        const float c1 = g_cmax[(size_t)(lane + 32) * N_ROWS + row];
        const float c2 = g_cmax[(size_t)(lane + 64) * N_ROWS + row];
        const float c3 = g_cmax[(size_t)(lane + 96) * N_ROWS + row];
        s_env[wslot][lane]      = c0;
        s_env[wslot][lane + 32] = c1;
        s_env[wslot][lane + 64] = c2;
        s_env[wslot][lane + 96] = c3;
        __syncwarp();

        float bm = fmaxf(fmaxf(c0, c1), fmaxf(c2, c3));
        #pragma unroll
        for (int s = 16; s > 0; s >>= 1)
            bm = fmaxf(bm, __shfl_xor_sync(0xffffffffu, bm, s));
        const float thr = bm - GTH;

        float xr[DIMS];
        {
            const float4* xp = (const float4*)(x + (size_t)row * DIMS);
            #pragma unroll
            for (int j = 0; j < DIMS / 4; j++) {
                float4 v = xp[j];
                xr[4 * j] = v.x; xr[4 * j + 1] = v.y;
                xr[4 * j + 2] = v.z; xr[4 * j + 3] = v.w;
            }
        }
        double xs;
        {
            float a = __ldg(x + (size_t)row * DIMS + 2 * lane);
            float b = __ldg(x + (size_t)row * DIMS + 2 * lane + 1);
            xs = (double)a * a + (double)b * b;
            #pragma unroll
            for (int off = 16; off > 0; off >>= 1)
                xs += __shfl_xor_sync(0xffffffffu, xs, off);
        }
        const float xnorm = (float)xs;

        float best = FLT_MAX;
        int   bi   = 0x7fffffff;
        for (int j = 0; j < NCHUNK2; j++) {
            if (s_env[wslot][j] < thr) continue;

            const int k = j * GN2 + lane;
            const float4* e4 = (const float4*)(cb + (size_t)k * DIMS);
            float acc = 0.0f;
            #pragma unroll
            for (int qd = 0; qd < DIMS / 4; qd++) {
                float4 E = e4[qd];
                acc = fmaf(xr[4 * qd + 0], E.x, acc);
                acc = fmaf(xr[4 * qd + 1], E.y, acc);
                acc = fmaf(xr[4 * qd + 2], E.z, acc);
                acc = fmaf(xr[4 * qd + 3], E.w, acc);
            }
            float dd = (xnorm + __ldg(&g_enorm[k])) - 2.0f * acc;
            if (dd < best) { best = dd; bi = k; }
        }
        #pragma unroll
        for (int s = 1; s < 32; s <<= 1) {
            float ob = __shfl_xor_sync(0xffffffffu, best, s);
            int   oi = __shfl_xor_sync(0xffffffffu, bi,   s);
            if (ob < best || (ob == best && oi < bi)) { best = ob; bi = oi; }
        }
        if (lane == 0) g_idx[row] = bi;
    }
}

// ---------- epilogue: gather winner, straight-through output, loss partials ----------
__global__ __launch_bounds__(ETHREADS)
void vq_epi(const float* __restrict__ x, const float* __restrict__ y,
            const float* __restrict__ cb, float* __restrict__ out) {
    __shared__ float s_red[ETHREADS / 32];

    const int tid = threadIdx.x;
    const int row = blockIdx.x * ETHREADS + tid;
    const int bidx = g_idx[row];

    float ls = 0.f;
    const float4* xp = (const float4*)(x  + (size_t)row  * DIMS);
    const float4* yp = (const float4*)(y  + (size_t)row  * DIMS);
    const float4* ep = (const float4*)(cb + (size_t)bidx * DIMS);
    float4*       op = (float4*)(out + (size_t)row * DIMS);

    #pragma unroll
    for (int i = 0; i < DIMS / 4; i++) {
        float4 xv = xp[i];
        float4 yv = yp[i];
        float4 e  = ep[i];

        float d;
        d = e.x - xv.x; ls += d * d;  d = e.x - yv.x; ls += d * d;
        d = e.y - xv.y; ls += d * d;  d = e.y - yv.y; ls += d * d;
        d = e.z - xv.z; ls += d * d;  d = e.z - yv.z; ls += d * d;
        d = e.w - xv.w; ls += d * d;  d = e.w - yv.w; ls += d * d;

        float4 o;
        float a;
        a = xv.x + yv.x; o.x = a + (e.x - a);
        a = xv.y + yv.y; o.y = a + (e.y - a);
        a = xv.z + yv.z; o.z = a + (e.z - a);
        a = xv.w + yv.w; o.w = a + (e.w - a);
        op[i] = o;
    }

    #pragma unroll
    for (int off = 16; off > 0; off >>= 1)
        ls += __shfl_xor_sync(0xffffffffu, ls, off);
    if ((tid & 31) == 0) s_red[tid >> 5] = ls;
    __syncthreads();
    if (tid == 0) {
        float s = 0.f;
        #pragma unroll
        for (int w = 0; w < ETHREADS / 32; w++) s += s_red[w];
        g_bsum[blockIdx.x] = s;
    }
}

__global__ void vq_fin(float* __restrict__ out) {
    if (threadIdx.x == 0 && blockIdx.x == 0) {
        double acc = 0.0;
        for (int i = 0; i < EBLOCKS; i++) acc += (double)g_bsum[i];
        double loss = 1.25 * acc / (double)((size_t)N_ROWS * DIMS);
        out[(size_t)N_ROWS * DIMS] = (float)loss;
    }
}

extern "C" void kernel_launch(void* const* d_in, const int* in_sizes, int n_in,
                              void* d_out, int out_size) {
    const float* x  = (const float*)d_in[0];
    const float* y  = (const float*)d_in[1];
    const float* cb = (const float*)d_in[2];
    float* out = (float*)d_out;

    static int smem_set = 0;
    if (!smem_set) {
        cudaFuncSetAttribute(vq_gemm1, cudaFuncAttributeMaxDynamicSharedMemorySize, SMEM1_TOTAL);
        smem_set = 1;
    }

    vq_init<<<(KENT + 255) / 256, 256>>>(cb);
    vq_prep_cb<<<(KENT * DIMS / 4 + 255) / 256, 256>>>(cb);
    vq_gemm1<<<GBLOCKS, 256, SMEM1_TOTAL>>>(x);
    vq_cand<<<256, 256>>>(x, cb);
    vq_epi<<<EBLOCKS, ETHREADS>>>(x, y, cb, out);
    vq_fin<<<1, 1>>>(out);
}

// round 17
// speedup vs baseline: 1.4584x; 1.2454x over previous
#include <cuda_runtime.h>
#include <cuda_fp16.h>
#include <cstdint>
#include <cfloat>

// Problem constants
#define N_ROWS  131072
#define DIMS    64
#define KENT    4096
#define GM      128            // rows per CTA
#define GNB     128            // codes per pipeline super-chunk
#define NSTEP   8              // 16-code steps per super-chunk
#define NBIG    (KENT / GNB)   // 32
#define GN2     32             // codes per cmax chunk (envelope granularity, validated)
#define NCHUNK2 (KENT / GN2)   // 128
#define GBLOCKS (N_ROWS / GM)  // 1024
#define ETHREADS 256
#define EROWS    2             // rows per thread in vq_epi
#define EBLOCKS (N_ROWS / (ETHREADS * EROWS))   // 256
#define TAU1    0.03f          // fp16 dist margin -> flagged for exact candidate rescore
#define GTH     0.04f          // g-scale chunk-candidate slack (~25 sigma)

// gemm1 smem
#define SROW1   144
#define A_BYTES (GM * SROW1)                  // 18432
#define B1_OFF  A_BYTES
#define B1_BYTES (GNB * SROW1)                // 18432 per buffer
#define EN1_OFF (B1_OFF + 2 * B1_BYTES)       // 55296
#define SMEM1_TOTAL (EN1_OFF + 2 * 512)       // 56320

// Scratch
__device__ __half g_bh[(size_t)KENT * DIMS];            // fp16 codebook, 512 KB
__device__ float  g_cmax[(size_t)NCHUNK2 * N_ROWS];     // CHUNK-MAJOR [chunk][row], 67 MB
__device__ float  g_enorm[KENT];
__device__ float  g_en2[KENT];
__device__ float  g_bsum[EBLOCKS];
__device__ int    g_idx[N_ROWS];
__device__ int    g_list[N_ROWS];
__device__ int    g_cnt;

// ---------------- helpers ----------------
__device__ __forceinline__ uint32_t smem_u32(const void* p) {
    uint32_t a;
    asm("{ .reg .u64 t; cvta.to.shared.u64 t, %1; cvt.u32.u64 %0, t; }" : "=r"(a) : "l"(p));
    return a;
}
#define CP_ASYNC16(dst, src) \
    asm volatile("cp.async.cg.shared.global [%0], [%1], 16;" :: "r"(dst), "l"(src))
#define CP_COMMIT() asm volatile("cp.async.commit_group;" ::: "memory")
#define CP_WAIT(n)  asm volatile("cp.async.wait_group %0;" :: "n"(n) : "memory")

#define LDSM4(r0, r1, r2, r3, a) \
    asm volatile("ldmatrix.sync.aligned.m8n8.x4.shared.b16 {%0,%1,%2,%3}, [%4];" \
        : "=r"(r0), "=r"(r1), "=r"(r2), "=r"(r3) : "r"(a))

// accumulate form
#define MMA16816(d, a, b0_, b1_) \
    asm volatile("mma.sync.aligned.m16n8k16.row.col.f32.f16.f16.f32 " \
        "{%0,%1,%2,%3}, {%4,%5,%6,%7}, {%8,%9}, {%0,%1,%2,%3};" \
        : "+f"((d)[0]), "+f"((d)[1]), "+f"((d)[2]), "+f"((d)[3]) \
        : "r"((a)[0]), "r"((a)[1]), "r"((a)[2]), "r"((a)[3]), "r"(b0_), "r"(b1_))

// init form: d = a*b + 0
#define MMA16816_Z(d, a, b0_, b1_) \
    asm volatile("mma.sync.aligned.m16n8k16.row.col.f32.f16.f16.f32 " \
        "{%0,%1,%2,%3}, {%4,%5,%6,%7}, {%8,%9}, {%10,%10,%10,%10};" \
        : "=f"((d)[0]), "=f"((d)[1]), "=f"((d)[2]), "=f"((d)[3]) \
        : "r"((a)[0]), "r"((a)[1]), "r"((a)[2]), "r"((a)[3]), "r"(b0_), "r"(b1_), "f"(0.0f))

__device__ __forceinline__ void upd(float& b, float& b2, int& id, float g, int c) {
    if (g > b) { b2 = b; b = g; id = c; }
    else if (g > b2) { b2 = g; }
}

// ---------- kernel 0: fused norms (fp64->fp32), -en/2, fp16 codebook, counter reset ----------
__global__ void vq_init_prep(const float* __restrict__ cb) {
    int k = blockIdx.x * blockDim.x + threadIdx.x;
    if (k == 0) g_cnt = 0;
    if (k < KENT) {
        const float4* p = (const float4*)(cb + (size_t)k * DIMS);
        __half2* o = (__half2*)(g_bh + (size_t)k * DIMS);
        double s = 0.0;
        #pragma unroll
        for (int i = 0; i < DIMS / 4; i++) {
            float4 v = p[i];
            s += (double)v.x * v.x + (double)v.y * v.y
               + (double)v.z * v.z + (double)v.w * v.w;
            o[2 * i]     = __floats2half2_rn(v.x, v.y);
            o[2 * i + 1] = __floats2half2_rn(v.z, v.w);
        }
        g_enorm[k] = (float)s;
        g_en2[k]   = (float)(-0.5 * s);
    }
}

// ---------- tier 0: fp16 HMMA GEMM, m16n16 warp tiles, 4 CTAs/SM ----------
// warp wid: rows wid*16..+15, 16 codes per step.
__global__ __launch_bounds__(256, 4)
void vq_gemm1(const float* __restrict__ x) {
    extern __shared__ char dsm[];
    const int tid  = threadIdx.x;
    const int wid  = tid >> 5;
    const int lane = tid & 31;
    const uint32_t S = smem_u32(dsm);

    {
        const int rbase = blockIdx.x * GM;
        for (int idx = tid; idx < GM * DIMS; idx += 256) {
            int r = idx >> 6, d = idx & 63;
            float v = x[(size_t)(rbase + r) * DIMS + d];
            *(__half*)(dsm + r * SROW1 + 2 * d) = __float2half_rn(v);
        }
    }
    {   // prologue: super-chunk 0 B + en2
        const char* Bg = (const char*)g_bh;
        for (int c = tid; c < GNB * 8; c += 256) {
            int rowb = c >> 3, seg = c & 7;
            CP_ASYNC16(S + B1_OFF + rowb * SROW1 + seg * 16, Bg + rowb * 128 + seg * 16);
        }
        if (tid < 32) CP_ASYNC16(S + EN1_OFF + tid * 16, (const char*)g_en2 + tid * 16);
        CP_COMMIT();
        CP_WAIT(0);
    }
    __syncthreads();

    uint32_t af[4][4];
    {
        uint32_t a_base = S + (uint32_t)(wid * 16 + (lane & 15)) * SROW1 + (uint32_t)(lane >> 4) * 16;
        #pragma unroll
        for (int k = 0; k < 4; k++)
            LDSM4(af[k][0], af[k][1], af[k][2], af[k][3], a_base + k * 32);
    }

    const uint32_t n_part = (lane & 7) + ((lane >> 4) & 1) * 8;   // 0..15 (B rows within 16)
    const uint32_t koff_b = ((lane >> 3) & 1) * 16;
    const int c4 = lane & 3;
    const int q  = lane >> 2;
    const int rowA_g = blockIdx.x * GM + wid * 16 + q;
    const int rowB_g = rowA_g + 8;

    float bestA = -FLT_MAX, best2A = -FLT_MAX;
    float bestB = -FLT_MAX, best2B = -FLT_MAX;
    int   idxA = 0, idxB = 0;
    float mpA = -FLT_MAX, mpB = -FLT_MAX;   // 16-code pair accumulators for 32-code cmax

    for (int i = 0; i < NBIG; i++) {
        const int buf = i & 1;
        if (i + 1 < NBIG) {
            const char* Bg = (const char*)(g_bh + (size_t)(i + 1) * GNB * DIMS);
            uint32_t Bs = S + B1_OFF + (buf ^ 1) * B1_BYTES;
            for (int c = tid; c < GNB * 8; c += 256) {
                int rowb = c >> 3, seg = c & 7;
                CP_ASYNC16(Bs + rowb * SROW1 + seg * 16, Bg + rowb * 128 + seg * 16);
            }
            if (tid < 32)
                CP_ASYNC16(S + EN1_OFF + (buf ^ 1) * 512 + tid * 16,
                           (const char*)(g_en2 + (i + 1) * GNB) + tid * 16);
            CP_COMMIT();
            CP_WAIT(1);
        } else {
            CP_WAIT(0);
        }
        __syncthreads();

        const uint32_t Bb = S + B1_OFF + buf * B1_BYTES;
        const float2* envb = (const float2*)(dsm + EN1_OFF + buf * 512);

        #pragma unroll
        for (int s = 0; s < NSTEP; s++) {
            const uint32_t Bs = Bb + (uint32_t)(s * 16) * SROW1;
            float d[2][4];
            {   // k = 0: init form
                uint32_t b0, b1, b2, b3;
                LDSM4(b0, b1, b2, b3, Bs + n_part * SROW1 + koff_b);
                MMA16816_Z(d[0], af[0], b0, b1);
                MMA16816_Z(d[1], af[0], b2, b3);
            }
            #pragma unroll
            for (int k = 1; k < 4; k++) {
                uint32_t b0, b1, b2, b3;
                LDSM4(b0, b1, b2, b3, Bs + n_part * SROW1 + k * 32 + koff_b);
                MMA16816(d[0], af[k], b0, b1);
                MMA16816(d[1], af[k], b2, b3);
            }

            // epilogue: g = d + en2; lazy top-2; pair-max for 32-code cmax
            const float2* env = envb + s * 8;       // 8 float2 per 16-code step
            float2 e0 = env[c4];
            float2 e1 = env[4 + c4];

            float mA = fmaxf(fmaxf(d[0][0] + e0.x, d[0][1] + e0.y),
                             fmaxf(d[1][0] + e1.x, d[1][1] + e1.y));
            float mB = fmaxf(fmaxf(d[0][2] + e0.x, d[0][3] + e0.y),
                             fmaxf(d[1][2] + e1.x, d[1][3] + e1.y));

            mA = fmaxf(mA, __shfl_xor_sync(0xffffffffu, mA, 1));
            mA = fmaxf(mA, __shfl_xor_sync(0xffffffffu, mA, 2));
            mB = fmaxf(mB, __shfl_xor_sync(0xffffffffu, mB, 1));
            mB = fmaxf(mB, __shfl_xor_sync(0xffffffffu, mB, 2));

            mpA = (s & 1) ? fmaxf(mpA, mA) : mA;
            mpB = (s & 1) ? fmaxf(mpB, mB) : mB;
            if ((s & 1) && c4 == 0) {
                const int chunk2 = i * (NSTEP / 2) + (s >> 1);
                g_cmax[(size_t)chunk2 * N_ROWS + rowA_g] = mpA;
                g_cmax[(size_t)chunk2 * N_ROWS + rowB_g] = mpB;
            }

            const int cbase = (i * NSTEP + s) * 16 + c4 * 2;
            if (mA > best2A) {
                upd(bestA, best2A, idxA, d[0][0] + e0.x, cbase);
                upd(bestA, best2A, idxA, d[0][1] + e0.y, cbase + 1);
                upd(bestA, best2A, idxA, d[1][0] + e1.x, cbase + 8);
                upd(bestA, best2A, idxA, d[1][1] + e1.y, cbase + 9);
            }
            if (mB > best2B) {
                upd(bestB, best2B, idxB, d[0][2] + e0.x, cbase);
                upd(bestB, best2B, idxB, d[0][3] + e0.y, cbase + 1);
                upd(bestB, best2B, idxB, d[1][2] + e1.x, cbase + 8);
                upd(bestB, best2B, idxB, d[1][3] + e1.y, cbase + 9);
            }
        }
        __syncthreads();   // protect buf^1 (B + en2) before next prefetch overwrites
    }

    #pragma unroll
    for (int s = 1; s <= 2; s <<= 1) {
        float ob  = __shfl_xor_sync(0xffffffffu, bestA,  s);
        float ob2 = __shfl_xor_sync(0xffffffffu, best2A, s);
        int   oi  = __shfl_xor_sync(0xffffffffu, idxA,   s);
        if (ob > bestA) { best2A = fmaxf(bestA, ob2); bestA = ob; idxA = oi; }
        else            { best2A = fmaxf(best2A, ob); }
        ob  = __shfl_xor_sync(0xffffffffu, bestB,  s);
        ob2 = __shfl_xor_sync(0xffffffffu, best2B, s);
        oi  = __shfl_xor_sync(0xffffffffu, idxB,   s);
        if (ob > bestB) { best2B = fmaxf(bestB, ob2); bestB = ob; idxB = oi; }
        else            { best2B = fmaxf(best2B, ob); }
    }

    if (c4 == 0) {
        g_idx[rowA_g] = idxA;
        g_idx[rowB_g] = idxB;
        if (2.0f * (bestA - best2A) < TAU1) { int s = atomicAdd(&g_cnt, 1); g_list[s] = rowA_g; }
        if (2.0f * (bestB - best2B) < TAU1) { int s = atomicAdd(&g_cnt, 1); g_list[s] = rowB_g; }
    }
}

// ---------- candidate rescore: bit-exact reference emulation over candidate chunks ----------
// 128 chunks of 32 codes; one code per lane per candidate chunk. (validated R15/R16)
__global__ __launch_bounds__(256)
void vq_cand(const float* __restrict__ x, const float* __restrict__ cb) {
    __shared__ float s_env[8][NCHUNK2];
    const int lane  = threadIdx.x & 31;
    const int wslot = threadIdx.x >> 5;
    const int gw    = (blockIdx.x * blockDim.x + threadIdx.x) >> 5;
    const int nw    = (gridDim.x * blockDim.x) >> 5;
    const int cnt   = g_cnt;

    for (int i = gw; i < cnt; i += nw) {
        const int row = g_list[i];

        __syncwarp();
        const float c0 = g_cmax[(size_t)lane * N_ROWS + row];
        const float c1 = g_cmax[(size_t)(lane + 32) * N_ROWS + row];
        const float c2 = g_cmax[(size_t)(lane + 64) * N_ROWS + row];
        const float c3 = g_cmax[(size_t)(lane + 96) * N_ROWS + row];
        s_env[wslot][lane]      = c0;
        s_env[wslot][lane + 32] = c1;
        s_env[wslot][lane + 64] = c2;
        s_env[wslot][lane + 96] = c3;
        __syncwarp();

        float bm = fmaxf(fmaxf(c0, c1), fmaxf(c2, c3));
        #pragma unroll
        for (int s = 16; s > 0; s >>= 1)
            bm = fmaxf(bm, __shfl_xor_sync(0xffffffffu, bm, s));
        const float thr = bm - GTH;

        float xr[DIMS];
        {
            const float4* xp = (const float4*)(x + (size_t)row * DIMS);
            #pragma unroll
            for (int j = 0; j < DIMS / 4; j++) {
                float4 v = xp[j];
                xr[4 * j] = v.x; xr[4 * j + 1] = v.y;
                xr[4 * j + 2] = v.z; xr[4 * j + 3] = v.w;
            }
        }
        double xs;
        {
            float a = __ldg(x + (size_t)row * DIMS + 2 * lane);
            float b = __ldg(x + (size_t)row * DIMS + 2 * lane + 1);
            xs = (double)a * a + (double)b * b;
            #pragma unroll
            for (int off = 16; off > 0; off >>= 1)
                xs += __shfl_xor_sync(0xffffffffu, xs, off);
        }
        const float xnorm = (float)xs;

        float best = FLT_MAX;
        int   bi   = 0x7fffffff;
        for (int j = 0; j < NCHUNK2; j++) {
            if (s_env[wslot][j] < thr) continue;

            const int k = j * GN2 + lane;
            const float4* e4 = (const float4*)(cb + (size_t)k * DIMS);
            float acc = 0.0f;
            #pragma unroll
            for (int qd = 0; qd < DIMS / 4; qd++) {
                float4 E = e4[qd];
                acc = fmaf(xr[4 * qd + 0], E.x, acc);
                acc = fmaf(xr[4 * qd + 1], E.y, acc);
                acc = fmaf(xr[4 * qd + 2], E.z, acc);
                acc = fmaf(xr[4 * qd + 3], E.w, acc);
            }
            float dd = (xnorm + __ldg(&g_enorm[k])) - 2.0f * acc;
            if (dd < best) { best = dd; bi = k; }
        }
        #pragma unroll
        for (int s = 1; s < 32; s <<= 1) {
            float ob = __shfl_xor_sync(0xffffffffu, best, s);
            int   oi = __shfl_xor_sync(0xffffffffu, bi,   s);
            if (ob < best || (ob == best && oi < bi)) { best = ob; bi = oi; }
        }
        if (lane == 0) g_idx[row] = bi;
    }
}

// ---------- epilogue: 2 rows/thread; gather winner, ST output, loss partials ----------
__global__ __launch_bounds__(ETHREADS)
void vq_epi(const float* __restrict__ x, const float* __restrict__ y,
            const float* __restrict__ cb, float* __restrict__ out) {
    __shared__ float s_red[ETHREADS / 32];

    const int tid  = threadIdx.x;
    const int row0 = blockIdx.x * (ETHREADS * EROWS) + tid;
    const int row1 = row0 + ETHREADS;
    const int b0 = g_idx[row0];
    const int b1 = g_idx[row1];

    float ls = 0.f;
    const float4* xp0 = (const float4*)(x  + (size_t)row0 * DIMS);
    const float4* yp0 = (const float4*)(y  + (size_t)row0 * DIMS);
    const float4* ep0 = (const float4*)(cb + (size_t)b0   * DIMS);
    float4*       op0 = (float4*)(out + (size_t)row0 * DIMS);
    const float4* xp1 = (const float4*)(x  + (size_t)row1 * DIMS);
    const float4* yp1 = (const float4*)(y  + (size_t)row1 * DIMS);
    const float4* ep1 = (const float4*)(cb + (size_t)b1   * DIMS);
    float4*       op1 = (float4*)(out + (size_t)row1 * DIMS);

    #pragma unroll
    for (int i = 0; i < DIMS / 4; i++) {
        float4 xv0 = xp0[i], yv0 = yp0[i], e0 = ep0[i];
        float4 xv1 = xp1[i], yv1 = yp1[i], e1 = ep1[i];

        float d;
        d = e0.x - xv0.x; ls += d * d;  d = e0.x - yv0.x; ls += d * d;
        d = e0.y - xv0.y; ls += d * d;  d = e0.y - yv0.y; ls += d * d;
        d = e0.z - xv0.z; ls += d * d;  d = e0.z - yv0.z; ls += d * d;
        d = e0.w - xv0.w; ls += d * d;  d = e0.w - yv0.w; ls += d * d;
        d = e1.x - xv1.x; ls += d * d;  d = e1.x - yv1.x; ls += d * d;
        d = e1.y - xv1.y; ls += d * d;  d = e1.y - yv1.y; ls += d * d;
        d = e1.z - xv1.z; ls += d * d;  d = e1.z - yv1.z; ls += d * d;
        d = e1.w - xv1.w; ls += d * d;  d = e1.w - yv1.w; ls += d * d;

        float4 o; float a;
        a = xv0.x + yv0.x; o.x = a + (e0.x - a);
        a = xv0.y + yv0.y; o.y = a + (e0.y - a);
        a = xv0.z + yv0.z; o.z = a + (e0.z - a);
        a = xv0.w + yv0.w; o.w = a + (e0.w - a);
        op0[i] = o;
        a = xv1.x + yv1.x; o.x = a + (e1.x - a);
        a = xv1.y + yv1.y; o.y = a + (e1.y - a);
        a = xv1.z + yv1.z; o.z = a + (e1.z - a);
        a = xv1.w + yv1.w; o.w = a + (e1.w - a);
        op1[i] = o;
    }

    #pragma unroll
    for (int off = 16; off > 0; off >>= 1)
        ls += __shfl_xor_sync(0xffffffffu, ls, off);
    if ((tid & 31) == 0) s_red[tid >> 5] = ls;
    __syncthreads();
    if (tid == 0) {
        float s = 0.f;
        #pragma unroll
        for (int w = 0; w < ETHREADS / 32; w++) s += s_red[w];
        g_bsum[blockIdx.x] = s;
    }
}

// ---------- deterministic final loss: fixed-tree parallel reduction ----------
__global__ void vq_fin(float* __restrict__ out) {
    __shared__ double s_acc[EBLOCKS];
    const int tid = threadIdx.x;        // 256 threads
    s_acc[tid] = (double)g_bsum[tid];
    __syncthreads();
    for (int off = EBLOCKS / 2; off > 0; off >>= 1) {
        if (tid < off) s_acc[tid] += s_acc[tid + off];   // fixed tree order
        __syncthreads();
    }
    if (tid == 0) {
        double loss = 1.25 * s_acc[0] / (double)((size_t)N_ROWS * DIMS);
        out[(size_t)N_ROWS * DIMS] = (float)loss;
    }
}

extern "C" void kernel_launch(void* const* d_in, const int* in_sizes, int n_in,
                              void* d_out, int out_size) {
    const float* x  = (const float*)d_in[0];
    const float* y  = (const float*)d_in[1];
    const float* cb = (const float*)d_in[2];
    float* out = (float*)d_out;

    static int smem_set = 0;
    if (!smem_set) {
        cudaFuncSetAttribute(vq_gemm1, cudaFuncAttributeMaxDynamicSharedMemorySize, SMEM1_TOTAL);
        smem_set = 1;
    }

    vq_init_prep<<<(KENT + 255) / 256, 256>>>(cb);
    vq_gemm1<<<GBLOCKS, 256, SMEM1_TOTAL>>>(x);
    vq_cand<<<256, 256>>>(x, cb);
    vq_epi<<<EBLOCKS, ETHREADS>>>(x, y, cb, out);
    vq_fin<<<1, EBLOCKS>>>(out);
}